// round 7
// baseline (speedup 1.0000x reference)
#include <cuda_runtime.h>
#include <cuda_bf16.h>
#include <math.h>
#include <stdint.h>

#define LSEQ   1024
#define DMODEL 1024
#define DINNER 2048
#define NSTATE 16
#define DTRANK 64
#define XDBLC  96     // dt_rank + 2*N = 64 + 32

// ---------------- fp32 scratch ----------------------------------------------
__device__ float g_xr   [LSEQ * 2 * DINNER];   // [L, 4096]  x@W_in (x_in | res)
__device__ float g_xconv[LSEQ * DINNER];       // [L, 2048]
__device__ float g_xdbl [LSEQ * XDBLC];        // [L, 96]
__device__ float g_delta[LSEQ * DINNER];       // [L, 2048]

// ---------------- bf16 hi/lo split buffers (16B aligned for cp.async) -------
__device__ __align__(16) __nv_bfloat16 g_xh[LSEQ * DMODEL],   g_xl[LSEQ * DMODEL];
__device__ __align__(16) __nv_bfloat16 g_Winh[2*DINNER*DMODEL], g_Winl[2*DINNER*DMODEL]; // [4096][1024] (W_in^T)
__device__ __align__(16) __nv_bfloat16 g_Wxh[XDBLC*DINNER],   g_Wxl[XDBLC*DINNER];       // [96][2048]  (W_x^T)
__device__ __align__(16) __nv_bfloat16 g_Wdth[DINNER*DTRANK], g_Wdtl[DINNER*DTRANK];     // [2048][64]  (W_dt^T)
__device__ __align__(16) __nv_bfloat16 g_Wouth[DMODEL*DINNER],g_Woutl[DMODEL*DINNER];    // [1024][2048](W_out^T)
__device__ __align__(16) __nv_bfloat16 g_xch[LSEQ*DINNER],    g_xcl[LSEQ*DINNER];
__device__ __align__(16) __nv_bfloat16 g_xdh[LSEQ*XDBLC],     g_xdl[LSEQ*XDBLC];
__device__ __align__(16) __nv_bfloat16 g_zh[LSEQ*DINNER],     g_zl[LSEQ*DINNER];

__device__ __forceinline__ float siluf(float x)     { return x / (1.0f + __expf(-x)); }
__device__ __forceinline__ float softplusf(float x) { return x > 20.0f ? x : log1pf(expf(x)); }

__device__ __forceinline__ uint32_t smem_u32(const void* p) {
    uint32_t a;
    asm("{ .reg .u64 t; cvta.to.shared.u64 t, %1; cvt.u32.u64 %0, t; }" : "=r"(a) : "l"(p));
    return a;
}

// ---------------- warp-level bf16 MMA (sm_80 baseline) ----------------------
__device__ __forceinline__ void mma16816(float c[4],
                                         uint32_t a0, uint32_t a1, uint32_t a2, uint32_t a3,
                                         uint32_t b0, uint32_t b1) {
    asm volatile(
        "mma.sync.aligned.m16n8k16.row.col.f32.bf16.bf16.f32 "
        "{%0,%1,%2,%3}, {%4,%5,%6,%7}, {%8,%9}, {%0,%1,%2,%3};"
        : "+f"(c[0]), "+f"(c[1]), "+f"(c[2]), "+f"(c[3])
        : "r"(a0), "r"(a1), "r"(a2), "r"(a3), "r"(b0), "r"(b1));
}

// ======================= pre-split bf16 GEMM (cp.async) =====================
// C[M,N] = A[M,K] * B^T where A given as hi/lo bf16 [M][K] (row-major, lda) and
// B given as hi/lo bf16 [N][K] (transposed weights, ldb). 3 cross-product MMAs.
// MODE 0: store. MODE 1: softplus(acc+bias[col]). MODE 2: atomicAdd (split-K z).
template<int BN, int MODE>
__global__ __launch_bounds__(256, 2) void gemm_bf16(
    int M, int N, int K,
    const __nv_bfloat16* __restrict__ Ah, const __nv_bfloat16* __restrict__ Al, int lda,
    const __nv_bfloat16* __restrict__ Bh, const __nv_bfloat16* __restrict__ Bl, int ldb,
    float* __restrict__ C, int ldc,
    const float* __restrict__ bias, int kChunk)
{
    constexpr int BM = 128, BK = 32;
    constexpr int AST   = 40;                 // smem row stride (bf16): conflict-free + 16B rows
    constexpr int A_ELE = BM * AST;           // 5120
    constexpr int B_ELE = BN * AST;
    constexpr int STAGE = 2 * A_ELE + 2 * B_ELE;   // Ah|Al|Bh|Bl (bf16 elems)
    constexpr int WN = BN / 2, NT = WN / 8;

    extern __shared__ __nv_bfloat16 sm[];
    const uint32_t smBase = smem_u32(sm);

    const int tid  = threadIdx.x;
    const int lane = tid & 31;
    const int wid  = tid >> 5;
    const int warpM = wid >> 1;               // 0..3
    const int warpN = wid & 1;                // 0..1
    const int rowBase = blockIdx.y * BM;
    const int colBase = blockIdx.x * BN;

    int k0 = 0;
    if (MODE == 2) k0 = blockIdx.z * kChunk;
    const int nch = (MODE == 2 ? kChunk : K) / BK;

    float acc[2][NT][4];
    #pragma unroll
    for (int mt = 0; mt < 2; mt++)
        #pragma unroll
        for (int nt = 0; nt < NT; nt++)
            #pragma unroll
            for (int j = 0; j < 4; j++) acc[mt][nt][j] = 0.0f;

    // ---- async copy one chunk (A/B hi+lo) into stage s
    auto issue = [&](int s, int kk) {
        const uint32_t sb = smBase + (uint32_t)(s * STAGE) * 2;
        #pragma unroll 2
        for (int e = tid; e < BM * 4; e += 256) {           // A: 128 rows x 4 x 16B
            int r = e >> 2, c = e & 3;
            const __nv_bfloat16* sh = Ah + (long)(rowBase + r) * lda + kk + c * 8;
            const __nv_bfloat16* sl = Al + (long)(rowBase + r) * lda + kk + c * 8;
            uint32_t d = sb + (uint32_t)(r * AST + c * 8) * 2;
            asm volatile("cp.async.ca.shared.global [%0], [%1], 16;" :: "r"(d), "l"(sh));
            asm volatile("cp.async.ca.shared.global [%0], [%1], 16;" :: "r"(d + A_ELE * 2), "l"(sl));
        }
        #pragma unroll 2
        for (int e = tid; e < BN * 4; e += 256) {           // B: BN rows x 4 x 16B
            int r = e >> 2, c = e & 3;
            const __nv_bfloat16* sh = Bh + (long)(colBase + r) * ldb + kk + c * 8;
            const __nv_bfloat16* sl = Bl + (long)(colBase + r) * ldb + kk + c * 8;
            uint32_t d = sb + (uint32_t)(2 * A_ELE + r * AST + c * 8) * 2;
            asm volatile("cp.async.ca.shared.global [%0], [%1], 16;" :: "r"(d), "l"(sh));
            asm volatile("cp.async.ca.shared.global [%0], [%1], 16;" :: "r"(d + B_ELE * 2), "l"(sl));
        }
    };

    auto compute = [&](int s) {
        const __nv_bfloat16* Abh = sm + s * STAGE;
        const __nv_bfloat16* Abl = Abh + A_ELE;
        const __nv_bfloat16* Bbh = Abl + A_ELE;
        const __nv_bfloat16* Bbl = Bbh + B_ELE;
        #pragma unroll
        for (int ks = 0; ks < 2; ks++) {
            const int kc = ks * 16 + (lane & 3) * 2;
            uint32_t ah[2][4], al[2][4];
            #pragma unroll
            for (int mt = 0; mt < 2; mt++) {
                int r = warpM * 32 + mt * 16 + (lane >> 2);
                ah[mt][0] = *reinterpret_cast<const uint32_t*>(&Abh[ r      * AST + kc    ]);
                ah[mt][1] = *reinterpret_cast<const uint32_t*>(&Abh[(r + 8) * AST + kc    ]);
                ah[mt][2] = *reinterpret_cast<const uint32_t*>(&Abh[ r      * AST + kc + 8]);
                ah[mt][3] = *reinterpret_cast<const uint32_t*>(&Abh[(r + 8) * AST + kc + 8]);
                al[mt][0] = *reinterpret_cast<const uint32_t*>(&Abl[ r      * AST + kc    ]);
                al[mt][1] = *reinterpret_cast<const uint32_t*>(&Abl[(r + 8) * AST + kc    ]);
                al[mt][2] = *reinterpret_cast<const uint32_t*>(&Abl[ r      * AST + kc + 8]);
                al[mt][3] = *reinterpret_cast<const uint32_t*>(&Abl[(r + 8) * AST + kc + 8]);
            }
            #pragma unroll
            for (int nt = 0; nt < NT; nt++) {
                int n = warpN * WN + nt * 8 + (lane >> 2);
                uint32_t bh0 = *reinterpret_cast<const uint32_t*>(&Bbh[n * AST + kc    ]);
                uint32_t bh1 = *reinterpret_cast<const uint32_t*>(&Bbh[n * AST + kc + 8]);
                uint32_t bl0 = *reinterpret_cast<const uint32_t*>(&Bbl[n * AST + kc    ]);
                uint32_t bl1 = *reinterpret_cast<const uint32_t*>(&Bbl[n * AST + kc + 8]);
                #pragma unroll
                for (int mt = 0; mt < 2; mt++) {
                    mma16816(acc[mt][nt], ah[mt][0], ah[mt][1], ah[mt][2], ah[mt][3], bh0, bh1);
                    mma16816(acc[mt][nt], al[mt][0], al[mt][1], al[mt][2], al[mt][3], bh0, bh1);
                    mma16816(acc[mt][nt], ah[mt][0], ah[mt][1], ah[mt][2], ah[mt][3], bl0, bl1);
                }
            }
        }
    };

    // ---- double-buffered async mainloop
    issue(0, k0);
    asm volatile("cp.async.commit_group;" ::: "memory");
    for (int ch = 0; ch < nch; ch++) {
        if (ch + 1 < nch) issue((ch + 1) & 1, k0 + (ch + 1) * BK);
        asm volatile("cp.async.commit_group;" ::: "memory");    // empty group on tail
        asm volatile("cp.async.wait_group 1;" ::: "memory");
        __syncthreads();
        compute(ch & 1);
        __syncthreads();
    }

    // ---- epilogue straight from accumulators
    #pragma unroll
    for (int mt = 0; mt < 2; mt++) {
        #pragma unroll
        for (int nt = 0; nt < NT; nt++) {
            int row = rowBase + warpM * 32 + mt * 16 + (lane >> 2);
            int col = colBase + warpN * WN + nt * 8 + (lane & 3) * 2;
            float v0 = acc[mt][nt][0], v1 = acc[mt][nt][1];
            float v2 = acc[mt][nt][2], v3 = acc[mt][nt][3];
            if (MODE == 1) {
                v0 = softplusf(v0 + bias[col]); v1 = softplusf(v1 + bias[col + 1]);
                v2 = softplusf(v2 + bias[col]); v3 = softplusf(v3 + bias[col + 1]);
            }
            if (MODE == 2) {
                atomicAdd(&C[ row      * ldc + col    ], v0);
                atomicAdd(&C[ row      * ldc + col + 1], v1);
                atomicAdd(&C[(row + 8) * ldc + col    ], v2);
                atomicAdd(&C[(row + 8) * ldc + col + 1], v3);
            } else {
                float2 p0; p0.x = v0; p0.y = v1;
                float2 p1; p1.x = v2; p1.y = v3;
                *reinterpret_cast<float2*>(&C[ row      * ldc + col]) = p0;
                *reinterpret_cast<float2*>(&C[(row + 8) * ldc + col]) = p1;
            }
        }
    }
}

// ---------------- fp32 -> bf16 hi/lo split ----------------------------------
__global__ void split_kernel(const float* __restrict__ s,
                             __nv_bfloat16* __restrict__ h,
                             __nv_bfloat16* __restrict__ l, int n)
{
    int i = blockIdx.x * blockDim.x + threadIdx.x;
    if (i < n) {
        float v = s[i];
        __nv_bfloat16 hv = __float2bfloat16(v);
        h[i] = hv;
        l[i] = __float2bfloat16(v - __bfloat162float(hv));
    }
}

// ---------------- transpose + split: src[R][C] fp32 -> dst[C][R] bf16 hi/lo --
__global__ void tsplit_kernel(const float* __restrict__ s,
                              __nv_bfloat16* __restrict__ h,
                              __nv_bfloat16* __restrict__ l, int R, int C)
{
    __shared__ float t[32][33];
    int tx = threadIdx.x, ty = threadIdx.y;
    int bx = blockIdx.x, by = blockIdx.y;
    #pragma unroll
    for (int i = 0; i < 4; i++)
        t[ty + 8 * i][tx] = s[(long)(by * 32 + ty + 8 * i) * C + bx * 32 + tx];
    __syncthreads();
    #pragma unroll
    for (int i = 0; i < 4; i++) {
        int c = bx * 32 + ty + 8 * i;
        int r = by * 32 + tx;
        float v = t[tx][ty + 8 * i];
        __nv_bfloat16 hv = __float2bfloat16(v);
        h[(long)c * R + r] = hv;
        l[(long)c * R + r] = __float2bfloat16(v - __bfloat162float(hv));
    }
}

// ---------------- zero small buffer -----------------------------------------
__global__ void zero_kernel(float* p, int n)
{
    int i = blockIdx.x * blockDim.x + threadIdx.x;
    if (i < n) p[i] = 0.0f;
}

// ---------------- causal depthwise conv (K=4) + SiLU (+ hi/lo out) ----------
__global__ void conv_silu_kernel(const float* __restrict__ conv_w,
                                 const float* __restrict__ conv_b)
{
    int idx = blockIdx.x * blockDim.x + threadIdx.x;
    if (idx >= LSEQ * DINNER) return;
    int d = idx & (DINNER - 1);
    int l = idx >> 11;
    float acc = conv_b[d];
    #pragma unroll
    for (int k = 0; k < 4; k++) {
        int ls = l - 3 + k;
        if (ls >= 0) acc += g_xr[(long)ls * (2 * DINNER) + d] * conv_w[d * 4 + k];
    }
    float sv = siluf(acc);
    g_xconv[idx] = sv;
    __nv_bfloat16 hv = __float2bfloat16(sv);
    g_xch[idx] = hv;
    g_xcl[idx] = __float2bfloat16(sv - __bfloat162float(hv));
}

// ---------------- selective scan (emits z as bf16 hi/lo) ---------------------
__global__ void scan_kernel(const float* __restrict__ A_log,
                            const float* __restrict__ Dvec)
{
    int gtid   = blockIdx.x * blockDim.x + threadIdx.x;
    int warpId = gtid >> 5;
    int lane   = threadIdx.x & 31;
    int grp    = lane >> 4;
    int n      = lane & 15;
    int d      = warpId * 2 + grp;
    if (d >= DINNER) return;

    const float Adn = -expf(A_log[d * NSTATE + n]);
    const float Dd  = Dvec[d];

    const float* pD = g_delta + d;
    const float* pU = g_xconv + d;
    const float* pB = g_xdbl + DTRANK + n;
    const float* pC = g_xdbl + DTRANK + NSTATE + n;
    const float* pR = g_xr + DINNER + d;

    float h = 0.0f;
    float dl = pD[0], u = pU[0], Bv = pB[0], Cv = pC[0];

    for (int l = 0; l < LSEQ; l++) {
        float dl2 = 0.f, u2 = 0.f, B2 = 0.f, C2 = 0.f;
        if (l + 1 < LSEQ) {
            dl2 = pD[(l + 1) * DINNER];
            u2  = pU[(l + 1) * DINNER];
            B2  = pB[(l + 1) * XDBLC];
            C2  = pC[(l + 1) * XDBLC];
        }
        float e = __expf(dl * Adn);
        h = fmaf(e, h, dl * Bv * u);

        float c = h * Cv;
        c += __shfl_xor_sync(0xffffffffu, c, 8);
        c += __shfl_xor_sync(0xffffffffu, c, 4);
        c += __shfl_xor_sync(0xffffffffu, c, 2);
        c += __shfl_xor_sync(0xffffffffu, c, 1);

        if (n == 0) {
            float y  = fmaf(u, Dd, c);
            float r  = pR[l * 2 * DINNER];
            float zf = y * siluf(r);
            __nv_bfloat16 zh = __float2bfloat16(zf);
            g_zh[l * DINNER + d] = zh;
            g_zl[l * DINNER + d] = __float2bfloat16(zf - __bfloat162float(zh));
        }
        dl = dl2; u = u2; Bv = B2; Cv = C2;
    }
}

// ---------------- launch ------------------------------------------------------
extern "C" void kernel_launch(void* const* d_in, const int* in_sizes, int n_in,
                              void* d_out, int out_size)
{
    const float* x      = (const float*)d_in[0];
    const float* W_in   = (const float*)d_in[1];
    const float* conv_w = (const float*)d_in[2];
    const float* conv_b = (const float*)d_in[3];
    const float* W_x    = (const float*)d_in[4];
    const float* W_dt   = (const float*)d_in[5];
    const float* b_dt   = (const float*)d_in[6];
    const float* A_log  = (const float*)d_in[7];
    const float* Dv     = (const float*)d_in[8];
    const float* W_out  = (const float*)d_in[9];
    float* out = (float*)d_out;

    float *xr, *xdbl, *delta;
    cudaGetSymbolAddress((void**)&xr,    g_xr);
    cudaGetSymbolAddress((void**)&xdbl,  g_xdbl);
    cudaGetSymbolAddress((void**)&delta, g_delta);

    __nv_bfloat16 *xh, *xl, *Winh, *Winl, *Wxh, *Wxl, *Wdth, *Wdtl, *Wouth, *Woutl;
    __nv_bfloat16 *xch, *xcl, *xdh, *xdl, *zh, *zl;
    cudaGetSymbolAddress((void**)&xh, g_xh);       cudaGetSymbolAddress((void**)&xl, g_xl);
    cudaGetSymbolAddress((void**)&Winh, g_Winh);   cudaGetSymbolAddress((void**)&Winl, g_Winl);
    cudaGetSymbolAddress((void**)&Wxh, g_Wxh);     cudaGetSymbolAddress((void**)&Wxl, g_Wxl);
    cudaGetSymbolAddress((void**)&Wdth, g_Wdth);   cudaGetSymbolAddress((void**)&Wdtl, g_Wdtl);
    cudaGetSymbolAddress((void**)&Wouth, g_Wouth); cudaGetSymbolAddress((void**)&Woutl, g_Woutl);
    cudaGetSymbolAddress((void**)&xch, g_xch);     cudaGetSymbolAddress((void**)&xcl, g_xcl);
    cudaGetSymbolAddress((void**)&xdh, g_xdh);     cudaGetSymbolAddress((void**)&xdl, g_xdl);
    cudaGetSymbolAddress((void**)&zh, g_zh);       cudaGetSymbolAddress((void**)&zl, g_zl);

    // dynamic smem: 2 stages * (2*128*40 + 2*BN*40) bf16 * 2B
    const int SMEM_128 = 2 * (2 * 128 * 40 + 2 * 128 * 40) * 2;  // 81920
    const int SMEM_96  = 2 * (2 * 128 * 40 + 2 *  96 * 40) * 2;  // 71680
    const int SMEM_64  = 2 * (2 * 128 * 40 + 2 *  64 * 40) * 2;  // 61440
    cudaFuncSetAttribute(gemm_bf16<128, 0>, cudaFuncAttributeMaxDynamicSharedMemorySize, SMEM_128);
    cudaFuncSetAttribute(gemm_bf16<128, 1>, cudaFuncAttributeMaxDynamicSharedMemorySize, SMEM_128);
    cudaFuncSetAttribute(gemm_bf16<96, 2>,  cudaFuncAttributeMaxDynamicSharedMemorySize, SMEM_96);
    cudaFuncSetAttribute(gemm_bf16<64, 0>,  cudaFuncAttributeMaxDynamicSharedMemorySize, SMEM_64);

    dim3 tb(32, 8);
    // ---- operand prep: transpose+split weights, split x
    tsplit_kernel<<<dim3(4096 / 32, 1024 / 32), tb>>>(W_in,  Winh,  Winl,  1024, 4096);
    tsplit_kernel<<<dim3(  96 / 32, 2048 / 32), tb>>>(W_x,   Wxh,   Wxl,   2048, 96);
    tsplit_kernel<<<dim3(2048 / 32,   64 / 32), tb>>>(W_dt,  Wdth,  Wdtl,  64,   2048);
    tsplit_kernel<<<dim3(1024 / 32, 2048 / 32), tb>>>(W_out, Wouth, Woutl, 2048, 1024);
    split_kernel<<<(LSEQ * DMODEL) / 256, 256>>>(x, xh, xl, LSEQ * DMODEL);

    // 1) x @ W_in -> xr [1024,4096]
    gemm_bf16<128, 0><<<dim3(4096 / 128, 1024 / 128), 256, SMEM_128>>>(
        1024, 4096, 1024, xh, xl, 1024, Winh, Winl, 1024, xr, 4096, nullptr, 0);

    // 2) conv + SiLU -> xconv fp32 + hi/lo
    conv_silu_kernel<<<(LSEQ * DINNER) / 256, 256>>>(conv_w, conv_b);

    // 3) xconv @ W_x -> xdbl [1024,96]  (split-K x8 atomic), then split
    zero_kernel<<<(LSEQ * XDBLC + 255) / 256, 256>>>(xdbl, LSEQ * XDBLC);
    gemm_bf16<96, 2><<<dim3(1, 1024 / 128, 8), 256, SMEM_96>>>(
        1024, XDBLC, 2048, xch, xcl, 2048, Wxh, Wxl, 2048, xdbl, XDBLC, nullptr, 256);
    split_kernel<<<(LSEQ * XDBLC + 255) / 256, 256>>>(xdbl, xdh, xdl, LSEQ * XDBLC);

    // 4) dt @ W_dt + b_dt, softplus -> delta [1024,2048]
    gemm_bf16<128, 1><<<dim3(2048 / 128, 1024 / 128), 256, SMEM_128>>>(
        1024, 2048, 64, xdh, xdl, XDBLC, Wdth, Wdtl, 64, delta, 2048, b_dt, 0);

    // 5) selective scan + gating -> z hi/lo [1024,2048]
    scan_kernel<<<256, 128>>>(A_log, Dv);

    // 6) z @ W_out -> out [1024,1024]
    gemm_bf16<64, 0><<<dim3(1024 / 64, 1024 / 128), 256, SMEM_64>>>(
        1024, 1024, 2048, zh, zl, 2048, Wouth, Woutl, 2048, out, 1024, nullptr, 0);
}